// round 1
// baseline (speedup 1.0000x reference)
#include <cuda_runtime.h>
#include <math_constants.h>

#define BB   4
#define TT   1024
#define EE   1024
#define HH   16
#define DD   64
#define BTC  4096                       // B*T
#define BHTD (BB*HH*TT*DD)              // 4,194,304

// Scratch (static device globals; no runtime allocation)
__device__ float g_q[2 * BHTD];
__device__ float g_k[2 * BHTD];
__device__ float g_v[2 * BHTD];
__device__ float g_ctx[2 * BTC * EE];

// ---------------------------------------------------------------------------
// Tiled SGEMM: C[m,n] = sum_k A[m,k] * W[n,k]   (A: M x 1024, W: N x 1024)
// BM=BN=128, BK=16, 256 threads, 8x8 per thread.
// mode 0: QKV projection — scatter epilogue into g_q/g_k/g_v[stream] ([b,h,t,d])
//         (column e of Wqkv decodes as e = di*48 + ki*16 + h)
// mode 1: output projection — A = g_ctx[stream], plain store to C
// ---------------------------------------------------------------------------
__global__ void __launch_bounds__(256) sgemm_kernel(
    const float* __restrict__ A, const float* __restrict__ W,
    float* __restrict__ C, int N, int mode, int stream)
{
    __shared__ float As[16][132];
    __shared__ float Ws[16][132];
    if (mode == 1) A = g_ctx + (size_t)stream * (BTC * EE);

    const int K = 1024;
    const int tid   = threadIdx.x;
    const int mBase = blockIdx.y << 7;
    const int nBase = blockIdx.x << 7;

    const int lrow = tid >> 2;          // 0..63
    const int lk   = (tid & 3) << 2;    // 0,4,8,12
    const int trow = (tid >> 4) << 3;   // 0..120
    const int tcol = (tid & 15) << 3;   // 0..120

    float acc[8][8];
#pragma unroll
    for (int i = 0; i < 8; i++)
#pragma unroll
        for (int j = 0; j < 8; j++) acc[i][j] = 0.f;

    for (int k0 = 0; k0 < K; k0 += 16) {
#pragma unroll
        for (int rr = 0; rr < 2; rr++) {
            int r = lrow + (rr << 6);
            float4 av = *(const float4*)&A[(size_t)(mBase + r) * K + k0 + lk];
            As[lk+0][r] = av.x; As[lk+1][r] = av.y;
            As[lk+2][r] = av.z; As[lk+3][r] = av.w;
            float4 wv = *(const float4*)&W[(size_t)(nBase + r) * K + k0 + lk];
            Ws[lk+0][r] = wv.x; Ws[lk+1][r] = wv.y;
            Ws[lk+2][r] = wv.z; Ws[lk+3][r] = wv.w;
        }
        __syncthreads();
#pragma unroll
        for (int kk = 0; kk < 16; kk++) {
            float a[8], b[8];
            *(float4*)&a[0] = *(const float4*)&As[kk][trow];
            *(float4*)&a[4] = *(const float4*)&As[kk][trow + 4];
            *(float4*)&b[0] = *(const float4*)&Ws[kk][tcol];
            *(float4*)&b[4] = *(const float4*)&Ws[kk][tcol + 4];
#pragma unroll
            for (int i = 0; i < 8; i++)
#pragma unroll
                for (int j = 0; j < 8; j++)
                    acc[i][j] += a[i] * b[j];
        }
        __syncthreads();
    }

    if (mode == 0) {
        float* qo = g_q + (size_t)stream * BHTD;
        float* ko = g_k + (size_t)stream * BHTD;
        float* vo = g_v + (size_t)stream * BHTD;
#pragma unroll
        for (int i = 0; i < 8; i++) {
            int m = mBase + trow + i;
            int b = m >> 10, t = m & 1023;
#pragma unroll
            for (int j = 0; j < 8; j++) {
                int n   = nBase + tcol + j;
                int di  = n / 48;
                int rem = n - di * 48;
                int ki  = rem >> 4;
                int h   = rem & 15;
                int idx = ((b * HH + h) * TT + t) * DD + di;
                float val = acc[i][j];
                if      (ki == 0) qo[idx] = val;
                else if (ki == 1) ko[idx] = val;
                else              vo[idx] = val;
            }
        }
    } else {
#pragma unroll
        for (int i = 0; i < 8; i++) {
            int m = mBase + trow + i;
            *(float4*)&C[(size_t)m * N + nBase + tcol] =
                make_float4(acc[i][0], acc[i][1], acc[i][2], acc[i][3]);
            *(float4*)&C[(size_t)m * N + nBase + tcol + 4] =
                make_float4(acc[i][4], acc[i][5], acc[i][6], acc[i][7]);
        }
    }
}

// ---------------------------------------------------------------------------
// Flash cross-attention. grid = (T/64, B*H, 2 output streams), 256 threads.
// Output stream o=0: xo = softmax(q2·k1/8)·v1 ; o=1: yo = softmax(q1·k2/8)·v2.
// Writes g_ctx[o] in [b, t, h*64+d] layout.
// Thread (ty,tx) of a 16x16 grid owns a 4x4 S/O sub-tile. Row stats reduced
// over the 16 lanes sharing a ty (contiguous half-warp) via shfl.xor.
// ---------------------------------------------------------------------------
#define ASTR 68

__global__ void __launch_bounds__(256) attn_kernel()
{
    extern __shared__ float sm[];
    float* Qs = sm;
    float* Ks = sm + 64 * ASTR;
    float* Vs = sm + 2 * 64 * ASTR;
    float* Ps = sm + 3 * 64 * ASTR;

    const int tid   = threadIdx.x;
    const int o     = blockIdx.z;
    const int bh    = blockIdx.y;
    const int qRow0 = blockIdx.x << 6;

    const float* qptr = g_q + (size_t)(1 - o) * BHTD + (size_t)bh * (TT * DD);
    const float* kptr = g_k + (size_t)o       * BHTD + (size_t)bh * (TT * DD);
    const float* vptr = g_v + (size_t)o       * BHTD + (size_t)bh * (TT * DD);

    const int ty4 = (tid >> 4) << 2;
    const int tx4 = (tid & 15) << 2;

    // Load the 64x64 Q tile
#pragma unroll
    for (int it = 0; it < 4; it++) {
        int idx = tid + (it << 8);
        int r   = idx >> 4;
        int c4  = (idx & 15) << 2;
        *(float4*)&Qs[r * ASTR + c4] =
            *(const float4*)&qptr[(qRow0 + r) * DD + c4];
    }

    float m_run[4], l_run[4], oacc[4][4];
#pragma unroll
    for (int i = 0; i < 4; i++) {
        m_run[i] = -CUDART_INF_F;
        l_run[i] = 0.f;
#pragma unroll
        for (int j = 0; j < 4; j++) oacc[i][j] = 0.f;
    }

    const float sc = 0.125f * 1.4426950408889634f;  // 1/sqrt(64) * log2(e)

    for (int t0 = 0; t0 < TT; t0 += 64) {
#pragma unroll
        for (int it = 0; it < 4; it++) {
            int idx = tid + (it << 8);
            int r   = idx >> 4;
            int c4  = (idx & 15) << 2;
            *(float4*)&Ks[r * ASTR + c4] = *(const float4*)&kptr[(t0 + r) * DD + c4];
            *(float4*)&Vs[r * ASTR + c4] = *(const float4*)&vptr[(t0 + r) * DD + c4];
        }
        __syncthreads();   // also covers the initial Q tile on the first pass

        float s[4][4];
#pragma unroll
        for (int i = 0; i < 4; i++)
#pragma unroll
            for (int j = 0; j < 4; j++) s[i][j] = 0.f;

#pragma unroll
        for (int d = 0; d < 64; d += 4) {
            float qf[4][4], kf[4][4];
#pragma unroll
            for (int i = 0; i < 4; i++) {
                float4 t = *(const float4*)&Qs[(ty4 + i) * ASTR + d];
                qf[i][0] = t.x; qf[i][1] = t.y; qf[i][2] = t.z; qf[i][3] = t.w;
            }
#pragma unroll
            for (int j = 0; j < 4; j++) {
                float4 t = *(const float4*)&Ks[(tx4 + j) * ASTR + d];
                kf[j][0] = t.x; kf[j][1] = t.y; kf[j][2] = t.z; kf[j][3] = t.w;
            }
#pragma unroll
            for (int i = 0; i < 4; i++)
#pragma unroll
                for (int j = 0; j < 4; j++)
#pragma unroll
                    for (int dd = 0; dd < 4; dd++)
                        s[i][j] += qf[i][dd] * kf[j][dd];
        }

        // online softmax (log2 domain)
#pragma unroll
        for (int i = 0; i < 4; i++) {
#pragma unroll
            for (int j = 0; j < 4; j++) s[i][j] *= sc;
            float mt = fmaxf(fmaxf(s[i][0], s[i][1]), fmaxf(s[i][2], s[i][3]));
#pragma unroll
            for (int off = 8; off; off >>= 1)
                mt = fmaxf(mt, __shfl_xor_sync(0xffffffffu, mt, off));
            float mnew = fmaxf(m_run[i], mt);
            float corr = exp2f(m_run[i] - mnew);
            m_run[i] = mnew;
            float rs = 0.f;
#pragma unroll
            for (int j = 0; j < 4; j++) {
                float p = exp2f(s[i][j] - mnew);
                s[i][j] = p;
                rs += p;
            }
#pragma unroll
            for (int off = 8; off; off >>= 1)
                rs += __shfl_xor_sync(0xffffffffu, rs, off);
            l_run[i] = l_run[i] * corr + rs;
#pragma unroll
            for (int j = 0; j < 4; j++) oacc[i][j] *= corr;
        }

        // stage P through shared, then O += P @ V
#pragma unroll
        for (int i = 0; i < 4; i++)
            *(float4*)&Ps[(ty4 + i) * ASTR + tx4] =
                make_float4(s[i][0], s[i][1], s[i][2], s[i][3]);
        __syncthreads();

#pragma unroll
        for (int cc = 0; cc < 64; cc += 4) {
            float vf[4][4];
#pragma unroll
            for (int r = 0; r < 4; r++) {
                float4 t = *(const float4*)&Vs[(cc + r) * ASTR + tx4];
                vf[r][0] = t.x; vf[r][1] = t.y; vf[r][2] = t.z; vf[r][3] = t.w;
            }
#pragma unroll
            for (int i = 0; i < 4; i++) {
                float4 p = *(const float4*)&Ps[(ty4 + i) * ASTR + cc];
#pragma unroll
                for (int j = 0; j < 4; j++)
                    oacc[i][j] += p.x * vf[0][j] + p.y * vf[1][j]
                                + p.z * vf[2][j] + p.w * vf[3][j];
            }
        }
        __syncthreads();   // protect Ks/Vs/Ps before next tile
    }

    const int b = bh >> 4;
    const int h = bh & 15;
    float* outp = g_ctx + (size_t)o * (BTC * EE);
#pragma unroll
    for (int i = 0; i < 4; i++) {
        float inv = 1.f / l_run[i];
        int row = qRow0 + ty4 + i;
        *(float4*)&outp[(size_t)(b * TT + row) * EE + h * DD + tx4] =
            make_float4(oacc[i][0] * inv, oacc[i][1] * inv,
                        oacc[i][2] * inv, oacc[i][3] * inv);
    }
}

// ---------------------------------------------------------------------------

extern "C" void kernel_launch(void* const* d_in, const int* in_sizes, int n_in,
                              void* d_out, int out_size)
{
    const float* x     = (const float*)d_in[0];
    const float* y     = (const float*)d_in[1];
    const float* Wqkv1 = (const float*)d_in[2];
    const float* Wqkv2 = (const float*)d_in[3];
    const float* Wout1 = (const float*)d_in[4];
    const float* Wout2 = (const float*)d_in[5];
    float* out = (float*)d_out;

    const int attn_smem = 4 * 64 * ASTR * (int)sizeof(float);   // 69632 B
    cudaFuncSetAttribute(attn_kernel,
                         cudaFuncAttributeMaxDynamicSharedMemorySize, attn_smem);

    dim3 blk(256);
    // QKV projections (with fused de-interleave to [b,h,t,d])
    sgemm_kernel<<<dim3(24, 32), blk>>>(x, Wqkv1, nullptr, 3072, 0, 0);
    sgemm_kernel<<<dim3(24, 32), blk>>>(y, Wqkv2, nullptr, 3072, 0, 1);
    // Cross attention (both directions in one grid)
    attn_kernel<<<dim3(16, 64, 2), blk, attn_smem>>>();
    // Output projections straight into d_out (xo@Wout1^T, then yo@Wout2^T)
    sgemm_kernel<<<dim3(8, 32), blk>>>(nullptr, Wout1, out, 1024, 1, 0);
    sgemm_kernel<<<dim3(8, 32), blk>>>(nullptr, Wout2, out + (size_t)BTC * EE, 1024, 1, 1);
}